// round 1
// baseline (speedup 1.0000x reference)
#include <cuda_runtime.h>
#include <cuda_bf16.h>
#include <cstdint>

#define N_NODES 50000
#define HD 128

// ---------------- scratch (device globals; no dynamic allocation) ----------
__device__ float g_dis[N_NODES];              // degree -> rsqrt(degree), in place
__device__ float g_xw[(size_t)N_NODES * HD];  // x @ W^T of current layer
__device__ float g_h1[(size_t)N_NODES * HD];  // layer-1 output
__device__ int   g_is64;                      // 1 if edge_index is int64, 0 if int32

// ---------------- small helpers --------------------------------------------
__global__ void init_kernel(float* deg, int n) {
    int i = blockIdx.x * blockDim.x + threadIdx.x;
    if (i == 0) g_is64 = 1;
    if (i < n) deg[i] = 1.0f;  // self-loop
}

// Inspect the first 2048 logical elements: if stored as int64 (little-endian),
// every odd 32-bit word is 0. Random int32 indices in [0,50000) make this
// impossible, so one nonzero odd word => int32. Reads stay within the buffer
// for BOTH interpretations (4096 words <= 1.2M words).
__global__ void detect_kernel(const int* __restrict__ ew) {
    for (int i = threadIdx.x; i < 2048; i += blockDim.x) {
        if (ew[2 * i + 1] != 0) g_is64 = 0;
    }
}

__global__ void deg_count_kernel(const int* __restrict__ ew, int E, float* deg) {
    int e = blockIdx.x * blockDim.x + threadIdx.x;
    if (e >= E) return;
    int d = g_is64 ? ew[2 * (E + e)] : ew[E + e];
    atomicAdd(&deg[d], 1.0f);
}

__global__ void rsqrt_kernel(float* dis, int n) {
    int i = blockIdx.x * blockDim.x + threadIdx.x;
    if (i < n) dis[i] = rsqrtf(dis[i]);
}

// ---------------- fused GEMM: XW = X @ W^T ; OUT = dis^2 * XW + b ----------
// Block tile 128 rows x 128 cols, 256 threads, 8x8 register tile per thread,
// packed f32x2 FMAs. Dynamic smem: Xs[128][129] + Wt[128][128] (transposed W).
#define GEMM_SMEM_BYTES ((128 * 129 + 128 * 128) * 4)

__global__ void __launch_bounds__(256, 1)
gcn_gemm(const float* __restrict__ X, const float* __restrict__ W,
         const float* __restrict__ bias, const float* __restrict__ dis,
         float* __restrict__ XW, float* __restrict__ OUT, int nrows)
{
    extern __shared__ float sm[];
    float* Xs = sm;               // [128][129] padded
    float* Wt = sm + 128 * 129;   // Wt[k*128 + c] = W[c*128 + k]

    const int tid  = threadIdx.x;
    const int row0 = blockIdx.x * 128;

    // Load W transposed into smem
    #pragma unroll
    for (int i = tid; i < 128 * 32; i += 256) {
        int c = i >> 5, kq = i & 31;
        float4 w4 = *((const float4*)W + c * 32 + kq);
        int k = kq << 2;
        Wt[(k + 0) * 128 + c] = w4.x;
        Wt[(k + 1) * 128 + c] = w4.y;
        Wt[(k + 2) * 128 + c] = w4.z;
        Wt[(k + 3) * 128 + c] = w4.w;
    }
    // Load X tile (zero-pad tail rows)
    #pragma unroll
    for (int i = tid; i < 128 * 32; i += 256) {
        int r = i >> 5, kq = i & 31;
        int gr = row0 + r;
        float4 v = make_float4(0.f, 0.f, 0.f, 0.f);
        if (gr < nrows) v = *((const float4*)X + (size_t)gr * 32 + kq);
        float* p = &Xs[r * 129 + (kq << 2)];
        p[0] = v.x; p[1] = v.y; p[2] = v.z; p[3] = v.w;
    }
    __syncthreads();

    const int tx = tid & 15;   // column group
    const int ty = tid >> 4;   // row group
    const int c0 = tx * 8;
    const float* xb = &Xs[(ty * 8) * 129];

    unsigned long long acc[8][4];
    #pragma unroll
    for (int r = 0; r < 8; r++)
        #pragma unroll
        for (int j = 0; j < 4; j++) acc[r][j] = 0ull;  // {0.f, 0.f}

    #pragma unroll 4
    for (int k = 0; k < 128; k++) {
        const unsigned long long* wrow = (const unsigned long long*)&Wt[k * 128 + c0];
        unsigned long long w0 = wrow[0], w1 = wrow[1], w2 = wrow[2], w3 = wrow[3];
        #pragma unroll
        for (int r = 0; r < 8; r++) {
            float xv = xb[r * 129 + k];
            unsigned long long xx;
            asm("mov.b64 %0, {%1, %1};" : "=l"(xx) : "f"(xv));
            asm("fma.rn.f32x2 %0, %1, %2, %0;" : "+l"(acc[r][0]) : "l"(xx), "l"(w0));
            asm("fma.rn.f32x2 %0, %1, %2, %0;" : "+l"(acc[r][1]) : "l"(xx), "l"(w1));
            asm("fma.rn.f32x2 %0, %1, %2, %0;" : "+l"(acc[r][2]) : "l"(xx), "l"(w2));
            asm("fma.rn.f32x2 %0, %1, %2, %0;" : "+l"(acc[r][3]) : "l"(xx), "l"(w3));
        }
    }

    float bv[8];
    #pragma unroll
    for (int j = 0; j < 8; j++) bv[j] = bias[c0 + j];

    #pragma unroll
    for (int r = 0; r < 8; r++) {
        int gr = row0 + ty * 8 + r;
        if (gr >= nrows) break;
        float ds = dis[gr];
        float sc = ds * ds;
        float v[8];
        #pragma unroll
        for (int j = 0; j < 4; j++) {
            float lo, hi;
            asm("mov.b64 {%0, %1}, %2;" : "=f"(lo), "=f"(hi) : "l"(acc[r][j]));
            v[2 * j] = lo; v[2 * j + 1] = hi;
        }
        float4* xwp = (float4*)&XW[(size_t)gr * HD + c0];
        xwp[0] = make_float4(v[0], v[1], v[2], v[3]);
        xwp[1] = make_float4(v[4], v[5], v[6], v[7]);
        float4* op = (float4*)&OUT[(size_t)gr * HD + c0];
        op[0] = make_float4(sc * v[0] + bv[0], sc * v[1] + bv[1],
                            sc * v[2] + bv[2], sc * v[3] + bv[3]);
        op[1] = make_float4(sc * v[4] + bv[4], sc * v[5] + bv[5],
                            sc * v[6] + bv[6], sc * v[7] + bv[7]);
    }
}

// ---------------- edge scatter: OUT[dst] += dis[src]*dis[dst] * XW[src] ----
// One warp per edge; each lane handles a float4; red.global.add.v4.f32.
__global__ void __launch_bounds__(256)
scatter_kernel(const int* __restrict__ ew, int E,
               const float* __restrict__ dis,
               const float* __restrict__ xw,
               float* __restrict__ out)
{
    int e = (int)((blockIdx.x * blockDim.x + threadIdx.x) >> 5);
    int lane = threadIdx.x & 31;
    if (e >= E) return;
    int s, d;
    if (g_is64) { s = ew[2 * e]; d = ew[2 * (E + e)]; }
    else        { s = ew[e];     d = ew[E + e]; }
    float nrm = dis[s] * dis[d];
    float4 v = *((const float4*)(xw + (size_t)s * HD) + lane);
    float* dp = out + (size_t)d * HD + lane * 4;
    asm volatile("red.global.add.v4.f32 [%0], {%1, %2, %3, %4};"
                 :: "l"(dp), "f"(v.x * nrm), "f"(v.y * nrm),
                    "f"(v.z * nrm), "f"(v.w * nrm)
                 : "memory");
}

// ---------------- launch ----------------------------------------------------
extern "C" void kernel_launch(void* const* d_in, const int* in_sizes, int n_in,
                              void* d_out, int out_size) {
    const float* emb = (const float*)d_in[0];
    const int*   ew  = (const int*)d_in[1];   // int32 view; width detected on device
    const float* W1  = (const float*)d_in[2];
    const float* b1  = (const float*)d_in[3];
    const float* W2  = (const float*)d_in[4];
    const float* b2  = (const float*)d_in[5];
    float* out = (float*)d_out;

    const int nrows = in_sizes[0] / HD;       // 50000
    const int E     = in_sizes[1] / 2;        // 600000

    float *dis_p, *xw_p, *h1_p;
    cudaGetSymbolAddress((void**)&dis_p, g_dis);
    cudaGetSymbolAddress((void**)&xw_p,  g_xw);
    cudaGetSymbolAddress((void**)&h1_p,  g_h1);

    cudaFuncSetAttribute(gcn_gemm, cudaFuncAttributeMaxDynamicSharedMemorySize,
                         GEMM_SMEM_BYTES);

    int nb_nodes = (nrows + 255) / 256;
    int nb_edges = (E + 255) / 256;
    int nb_scat  = (E + 7) / 8;               // 8 warps (edges) per 256-thread block
    int nb_gemm  = (nrows + 127) / 128;

    init_kernel<<<nb_nodes, 256>>>(dis_p, nrows);
    detect_kernel<<<1, 256>>>(ew);
    deg_count_kernel<<<nb_edges, 256>>>(ew, E, dis_p);
    rsqrt_kernel<<<nb_nodes, 256>>>(dis_p, nrows);

    // Layer 1
    gcn_gemm<<<nb_gemm, 256, GEMM_SMEM_BYTES>>>(emb, W1, b1, dis_p, xw_p, h1_p, nrows);
    scatter_kernel<<<nb_scat, 256>>>(ew, E, dis_p, xw_p, h1_p);

    // Layer 2
    gcn_gemm<<<nb_gemm, 256, GEMM_SMEM_BYTES>>>(h1_p, W2, b2, dis_p, xw_p, out, nrows);
    scatter_kernel<<<nb_scat, 256>>>(ew, E, dis_p, xw_p, out);
}

// round 2
// speedup vs baseline: 1.3276x; 1.3276x over previous
#include <cuda_runtime.h>
#include <cuda_bf16.h>
#include <cstdint>

#define N_NODES 50000
#define HD 128
#define E_MAX 600000

// ---------------- scratch (device globals; no dynamic allocation) ----------
__device__ float g_dis[N_NODES];                 // rsqrt(degree incl. self-loop)
__device__ int   g_cnt[N_NODES];                 // in-degree histogram (edges only)
__device__ int   g_rowptr[N_NODES + 1];          // CSR row pointers
__device__ int   g_cursor[N_NODES];              // fill cursors
__device__ int   g_bsum[256];                    // scan block sums
__device__ int2  g_csr[E_MAX];                   // packed (src, norm) per edge, dst-sorted
__device__ float g_xw[(size_t)N_NODES * HD];     // x @ W^T of current layer
__device__ float g_h1[(size_t)N_NODES * HD];     // layer-1 output
__device__ int   g_is64;                         // 1 if edge_index stored as int64

// ---------------- small helpers --------------------------------------------
__global__ void init_kernel(int n) {
    int i = blockIdx.x * blockDim.x + threadIdx.x;
    if (i == 0) g_is64 = 1;
    if (i < n) g_cnt[i] = 0;
}

// int64 little-endian => odd 32-bit words of first 2048 elems are all 0.
__global__ void detect_kernel(const int* __restrict__ ew) {
    for (int i = threadIdx.x; i < 2048; i += blockDim.x)
        if (ew[2 * i + 1] != 0) g_is64 = 0;
}

__global__ void hist_kernel(const int* __restrict__ ew, int E) {
    int e = blockIdx.x * blockDim.x + threadIdx.x;
    if (e >= E) return;
    int d = g_is64 ? ew[2 * (E + e)] : ew[E + e];
    atomicAdd(&g_cnt[d], 1);
}

__global__ void dis_kernel(int n) {
    int i = blockIdx.x * blockDim.x + threadIdx.x;
    if (i < n) g_dis[i] = rsqrtf((float)(g_cnt[i] + 1));
}

// ---- exclusive scan of g_cnt -> g_rowptr (3 kernels) ----
__global__ void scanA_kernel(int n) {
    __shared__ int sm[256];
    int i = blockIdx.x * 256 + threadIdx.x;
    int v = (i < n) ? g_cnt[i] : 0;
    sm[threadIdx.x] = v;
    __syncthreads();
    #pragma unroll
    for (int off = 1; off < 256; off <<= 1) {
        int t = (threadIdx.x >= off) ? sm[threadIdx.x - off] : 0;
        __syncthreads();
        sm[threadIdx.x] += t;
        __syncthreads();
    }
    if (i < n) g_rowptr[i] = sm[threadIdx.x] - v;  // exclusive, block-local
    if (threadIdx.x == 255) g_bsum[blockIdx.x] = sm[255];
}

__global__ void scanB_kernel(int nb) {
    __shared__ int sm[256];
    int v = (threadIdx.x < nb) ? g_bsum[threadIdx.x] : 0;
    sm[threadIdx.x] = v;
    __syncthreads();
    #pragma unroll
    for (int off = 1; off < 256; off <<= 1) {
        int t = (threadIdx.x >= off) ? sm[threadIdx.x - off] : 0;
        __syncthreads();
        sm[threadIdx.x] += t;
        __syncthreads();
    }
    if (threadIdx.x < nb) g_bsum[threadIdx.x] = sm[threadIdx.x] - v;  // exclusive
}

__global__ void scanC_kernel(int n, int E) {
    int i = blockIdx.x * 256 + threadIdx.x;
    if (i < n) {
        int rp = g_rowptr[i] + g_bsum[blockIdx.x];
        g_rowptr[i] = rp;
        g_cursor[i] = rp;
    }
    if (i == 0) g_rowptr[n] = E;
}

__global__ void fill_kernel(const int* __restrict__ ew, int E) {
    int e = blockIdx.x * blockDim.x + threadIdx.x;
    if (e >= E) return;
    int s, d;
    if (g_is64) { s = ew[2 * e]; d = ew[2 * (E + e)]; }
    else        { s = ew[e];     d = ew[E + e]; }
    int pos = atomicAdd(&g_cursor[d], 1);
    float nm = g_dis[s] * g_dis[d];
    g_csr[pos] = make_int2(s, __float_as_int(nm));
}

// ---------------- GEMM: XW = X @ W^T ---------------------------------------
// 128x128 tile, 256 threads, 8x8 reg tile, f32x2 FMAs.
// Xsd stores x pre-duplicated as (x,x) 64-bit pairs; Wt transposed, LDS.128.
#define GEMM_SMEM_BYTES (128 * 128 * 8 + 128 * 128 * 4)   // 192 KB

__global__ void __launch_bounds__(256, 1)
gcn_gemm(const float* __restrict__ X, const float* __restrict__ W,
         float* __restrict__ XW, int nrows)
{
    extern __shared__ char smraw[];
    unsigned long long* Xsd = (unsigned long long*)smraw;          // [128][128] (x,x)
    float* Wt = (float*)(smraw + 128 * 128 * 8);                   // Wt[k][c]

    const int tid  = threadIdx.x;
    const int row0 = blockIdx.x * 128;

    // W transposed into smem
    #pragma unroll
    for (int i = tid; i < 128 * 32; i += 256) {
        int c = i >> 5, kq = i & 31;
        float4 w4 = *((const float4*)W + c * 32 + kq);
        int k = kq << 2;
        Wt[(k + 0) * 128 + c] = w4.x;
        Wt[(k + 1) * 128 + c] = w4.y;
        Wt[(k + 2) * 128 + c] = w4.z;
        Wt[(k + 3) * 128 + c] = w4.w;
    }
    // X tile, duplicated per element
    #pragma unroll
    for (int i = tid; i < 128 * 32; i += 256) {
        int r = i >> 5, kq = i & 31;
        int gr = row0 + r;
        float4 v = make_float4(0.f, 0.f, 0.f, 0.f);
        if (gr < nrows) v = *((const float4*)X + (size_t)gr * 32 + kq);
        unsigned long long d0, d1, d2, d3;
        asm("mov.b64 %0, {%1, %1};" : "=l"(d0) : "f"(v.x));
        asm("mov.b64 %0, {%1, %1};" : "=l"(d1) : "f"(v.y));
        asm("mov.b64 %0, {%1, %1};" : "=l"(d2) : "f"(v.z));
        asm("mov.b64 %0, {%1, %1};" : "=l"(d3) : "f"(v.w));
        unsigned long long* p = &Xsd[r * 128 + (kq << 2)];
        p[0] = d0; p[1] = d1; p[2] = d2; p[3] = d3;
    }
    __syncthreads();

    const int tx = tid & 15;
    const int ty = tid >> 4;
    const int c0 = tx * 8;
    const unsigned long long* xb = &Xsd[(ty * 8) * 128];

    unsigned long long acc[8][4];
    #pragma unroll
    for (int r = 0; r < 8; r++)
        #pragma unroll
        for (int j = 0; j < 4; j++) acc[r][j] = 0ull;

    #pragma unroll 4
    for (int k = 0; k < 128; k++) {
        const ulonglong2* wrow = (const ulonglong2*)&Wt[k * 128 + c0];
        ulonglong2 wa = wrow[0], wb = wrow[1];
        #pragma unroll
        for (int r = 0; r < 8; r++) {
            unsigned long long xx = xb[r * 128 + k];
            asm("fma.rn.f32x2 %0, %1, %2, %0;" : "+l"(acc[r][0]) : "l"(xx), "l"(wa.x));
            asm("fma.rn.f32x2 %0, %1, %2, %0;" : "+l"(acc[r][1]) : "l"(xx), "l"(wa.y));
            asm("fma.rn.f32x2 %0, %1, %2, %0;" : "+l"(acc[r][2]) : "l"(xx), "l"(wb.x));
            asm("fma.rn.f32x2 %0, %1, %2, %0;" : "+l"(acc[r][3]) : "l"(xx), "l"(wb.y));
        }
    }

    #pragma unroll
    for (int r = 0; r < 8; r++) {
        int gr = row0 + ty * 8 + r;
        if (gr >= nrows) break;
        float v[8];
        #pragma unroll
        for (int j = 0; j < 4; j++) {
            float lo, hi;
            asm("mov.b64 {%0, %1}, %2;" : "=f"(lo), "=f"(hi) : "l"(acc[r][j]));
            v[2 * j] = lo; v[2 * j + 1] = hi;
        }
        float4* xwp = (float4*)&XW[(size_t)gr * HD + c0];
        xwp[0] = make_float4(v[0], v[1], v[2], v[3]);
        xwp[1] = make_float4(v[4], v[5], v[6], v[7]);
    }
}

// ---------------- aggregation: out[d] = b + dis[d]^2*xw[d] + sum norm*xw[s] -
// One warp per destination node; lane handles one float4 (4 columns).
__global__ void __launch_bounds__(256)
aggregate_kernel(const float* __restrict__ bias,
                 const float* __restrict__ xw,
                 float* __restrict__ out, int n)
{
    int node = blockIdx.x * 8 + (threadIdx.x >> 5);
    int lane = threadIdx.x & 31;
    if (node >= n) return;

    int beg = g_rowptr[node];
    int end = g_rowptr[node + 1];

    float ds = g_dis[node];
    float sc = ds * ds;
    float4 vs = ((const float4*)(xw + (size_t)node * HD))[lane];
    float4 b4 = ((const float4*)bias)[lane];
    float4 acc;
    acc.x = fmaf(sc, vs.x, b4.x);
    acc.y = fmaf(sc, vs.y, b4.y);
    acc.z = fmaf(sc, vs.z, b4.z);
    acc.w = fmaf(sc, vs.w, b4.w);

    int p = beg;
    for (; p + 4 <= end; p += 4) {
        int2 e0 = g_csr[p + 0];
        int2 e1 = g_csr[p + 1];
        int2 e2 = g_csr[p + 2];
        int2 e3 = g_csr[p + 3];
        float4 v0 = ((const float4*)(xw + (size_t)e0.x * HD))[lane];
        float4 v1 = ((const float4*)(xw + (size_t)e1.x * HD))[lane];
        float4 v2 = ((const float4*)(xw + (size_t)e2.x * HD))[lane];
        float4 v3 = ((const float4*)(xw + (size_t)e3.x * HD))[lane];
        float n0 = __int_as_float(e0.y), n1 = __int_as_float(e1.y);
        float n2 = __int_as_float(e2.y), n3 = __int_as_float(e3.y);
        acc.x = fmaf(n0, v0.x, acc.x); acc.y = fmaf(n0, v0.y, acc.y);
        acc.z = fmaf(n0, v0.z, acc.z); acc.w = fmaf(n0, v0.w, acc.w);
        acc.x = fmaf(n1, v1.x, acc.x); acc.y = fmaf(n1, v1.y, acc.y);
        acc.z = fmaf(n1, v1.z, acc.z); acc.w = fmaf(n1, v1.w, acc.w);
        acc.x = fmaf(n2, v2.x, acc.x); acc.y = fmaf(n2, v2.y, acc.y);
        acc.z = fmaf(n2, v2.z, acc.z); acc.w = fmaf(n2, v2.w, acc.w);
        acc.x = fmaf(n3, v3.x, acc.x); acc.y = fmaf(n3, v3.y, acc.y);
        acc.z = fmaf(n3, v3.z, acc.z); acc.w = fmaf(n3, v3.w, acc.w);
    }
    for (; p < end; p++) {
        int2 e = g_csr[p];
        float4 v = ((const float4*)(xw + (size_t)e.x * HD))[lane];
        float nm = __int_as_float(e.y);
        acc.x = fmaf(nm, v.x, acc.x); acc.y = fmaf(nm, v.y, acc.y);
        acc.z = fmaf(nm, v.z, acc.z); acc.w = fmaf(nm, v.w, acc.w);
    }

    ((float4*)(out + (size_t)node * HD))[lane] = acc;
}

// ---------------- launch ----------------------------------------------------
extern "C" void kernel_launch(void* const* d_in, const int* in_sizes, int n_in,
                              void* d_out, int out_size) {
    const float* emb = (const float*)d_in[0];
    const int*   ew  = (const int*)d_in[1];   // width detected on device
    const float* W1  = (const float*)d_in[2];
    const float* b1  = (const float*)d_in[3];
    const float* W2  = (const float*)d_in[4];
    const float* b2  = (const float*)d_in[5];
    float* out = (float*)d_out;

    const int nrows = in_sizes[0] / HD;       // 50000
    const int E     = in_sizes[1] / 2;        // 600000

    float *xw_p, *h1_p;
    cudaGetSymbolAddress((void**)&xw_p, g_xw);
    cudaGetSymbolAddress((void**)&h1_p, g_h1);

    cudaFuncSetAttribute(gcn_gemm, cudaFuncAttributeMaxDynamicSharedMemorySize,
                         GEMM_SMEM_BYTES);

    const int nb_nodes = (nrows + 255) / 256;   // 196
    const int nb_edges = (E + 255) / 256;       // 2344
    const int nb_gemm  = (nrows + 127) / 128;   // 391
    const int nb_agg   = (nrows + 7) / 8;       // 6250

    // ---- CSR build (shared by both layers) ----
    init_kernel<<<nb_nodes, 256>>>(nrows);
    detect_kernel<<<1, 256>>>(ew);
    hist_kernel<<<nb_edges, 256>>>(ew, E);
    dis_kernel<<<nb_nodes, 256>>>(nrows);
    scanA_kernel<<<nb_nodes, 256>>>(nrows);
    scanB_kernel<<<1, 256>>>(nb_nodes);
    scanC_kernel<<<nb_nodes, 256>>>(nrows, E);
    fill_kernel<<<nb_edges, 256>>>(ew, E);

    // ---- Layer 1 ----
    gcn_gemm<<<nb_gemm, 256, GEMM_SMEM_BYTES>>>(emb, W1, xw_p, nrows);
    aggregate_kernel<<<nb_agg, 256>>>(b1, xw_p, h1_p, nrows);

    // ---- Layer 2 ----
    gcn_gemm<<<nb_gemm, 256, GEMM_SMEM_BYTES>>>(h1_p, W2, xw_p, nrows);
    aggregate_kernel<<<nb_agg, 256>>>(b2, xw_p, out, nrows);
}

// round 3
// speedup vs baseline: 1.3933x; 1.0495x over previous
#include <cuda_runtime.h>
#include <cuda_bf16.h>
#include <cstdint>

#define N_NODES 50000
#define HD 128
#define E_MAX 600000

// ---------------- scratch (device globals; no dynamic allocation) ----------
__device__ float g_dis[N_NODES];                 // rsqrt(degree incl. self-loop)
__device__ int   g_cnt[N_NODES];                 // in-degree histogram (edges only)
__device__ int   g_rowptr[N_NODES + 1];          // CSR row pointers
__device__ int   g_cursor[N_NODES];              // fill cursors
__device__ int   g_bsum[256];                    // scan block sums
__device__ int2  g_csr[E_MAX];                   // packed (src, norm) per edge, dst-sorted
__device__ float g_xw[(size_t)N_NODES * HD];     // x @ W^T of current layer
__device__ float g_h1[(size_t)N_NODES * HD];     // layer-1 output
__device__ int   g_is64;                         // 1 if edge_index stored as int64

// ---------------- init + dtype detect (merged) ------------------------------
// Block 0 additionally detects index width: int64 little-endian => odd 32-bit
// words of the first 2048 logical elements are all zero (random int32 indices
// make that impossible). Reads stay in-bounds for both interpretations.
__global__ void initdetect_kernel(const int* __restrict__ ew, int n) {
    int i = blockIdx.x * blockDim.x + threadIdx.x;
    if (i < n) g_cnt[i] = 0;
    if (blockIdx.x == 0) {
        __shared__ int found;
        if (threadIdx.x == 0) found = 0;
        __syncthreads();
        int f = 0;
        for (int j = threadIdx.x; j < 2048; j += blockDim.x)
            if (ew[2 * j + 1] != 0) f = 1;
        if (f) atomicOr(&found, 1);
        __syncthreads();
        if (threadIdx.x == 0) g_is64 = found ? 0 : 1;
    }
}

__global__ void hist_kernel(const int* __restrict__ ew, int E) {
    int e = blockIdx.x * blockDim.x + threadIdx.x;
    if (e >= E) return;
    int d = g_is64 ? ew[2 * (E + e)] : ew[E + e];
    atomicAdd(&g_cnt[d], 1);
}

// ---- exclusive scan of g_cnt -> g_rowptr; also emits g_dis -----------------
__global__ void scanA_kernel(int n) {
    __shared__ int sm[256];
    int i = blockIdx.x * 256 + threadIdx.x;
    int v = (i < n) ? g_cnt[i] : 0;
    if (i < n) g_dis[i] = rsqrtf((float)(v + 1));
    sm[threadIdx.x] = v;
    __syncthreads();
    #pragma unroll
    for (int off = 1; off < 256; off <<= 1) {
        int t = (threadIdx.x >= off) ? sm[threadIdx.x - off] : 0;
        __syncthreads();
        sm[threadIdx.x] += t;
        __syncthreads();
    }
    if (i < n) g_rowptr[i] = sm[threadIdx.x] - v;  // exclusive, block-local
    if (threadIdx.x == 255) g_bsum[blockIdx.x] = sm[255];
}

__global__ void scanB_kernel(int nb) {
    __shared__ int sm[256];
    int v = (threadIdx.x < nb) ? g_bsum[threadIdx.x] : 0;
    sm[threadIdx.x] = v;
    __syncthreads();
    #pragma unroll
    for (int off = 1; off < 256; off <<= 1) {
        int t = (threadIdx.x >= off) ? sm[threadIdx.x - off] : 0;
        __syncthreads();
        sm[threadIdx.x] += t;
        __syncthreads();
    }
    if (threadIdx.x < nb) g_bsum[threadIdx.x] = sm[threadIdx.x] - v;  // exclusive
}

__global__ void scanC_kernel(int n, int E) {
    int i = blockIdx.x * 256 + threadIdx.x;
    if (i < n) {
        int rp = g_rowptr[i] + g_bsum[blockIdx.x];
        g_rowptr[i] = rp;
        g_cursor[i] = rp;
    }
    if (i == 0) g_rowptr[n] = E;
}

__global__ void fill_kernel(const int* __restrict__ ew, int E) {
    int e = blockIdx.x * blockDim.x + threadIdx.x;
    if (e >= E) return;
    int s, d;
    if (g_is64) { s = ew[2 * e]; d = ew[2 * (E + e)]; }
    else        { s = ew[e];     d = ew[E + e]; }
    int pos = atomicAdd(&g_cursor[d], 1);
    float nm = g_dis[s] * g_dis[d];
    g_csr[pos] = make_int2(s, __float_as_int(nm));
}

// ---------------- GEMM: XW = X @ W^T ---------------------------------------
// 128x128 tile, 256 threads, 8x8 reg tile, f32x2 FMAs.
// Balanced smem traffic: x read as scalar broadcast LDS.32 (dup in registers),
// W transposed and read via LDS.128.
#define GEMM_SMEM_BYTES ((128 * 129 + 128 * 128) * 4)   // ~131.5 KB

__global__ void __launch_bounds__(256, 1)
gcn_gemm(const float* __restrict__ X, const float* __restrict__ W,
         float* __restrict__ XW, int nrows)
{
    extern __shared__ float sm[];
    float* Xs = sm;               // [128][129] padded
    float* Wt = sm + 128 * 129;   // Wt[k][c] = W[c][k]

    const int tid  = threadIdx.x;
    const int row0 = blockIdx.x * 128;

    // W transposed into smem
    #pragma unroll
    for (int i = tid; i < 128 * 32; i += 256) {
        int c = i >> 5, kq = i & 31;
        float4 w4 = *((const float4*)W + c * 32 + kq);
        int k = kq << 2;
        Wt[(k + 0) * 128 + c] = w4.x;
        Wt[(k + 1) * 128 + c] = w4.y;
        Wt[(k + 2) * 128 + c] = w4.z;
        Wt[(k + 3) * 128 + c] = w4.w;
    }
    // X tile (zero-pad tail rows)
    #pragma unroll
    for (int i = tid; i < 128 * 32; i += 256) {
        int r = i >> 5, kq = i & 31;
        int gr = row0 + r;
        float4 v = make_float4(0.f, 0.f, 0.f, 0.f);
        if (gr < nrows) v = *((const float4*)X + (size_t)gr * 32 + kq);
        float* p = &Xs[r * 129 + (kq << 2)];
        p[0] = v.x; p[1] = v.y; p[2] = v.z; p[3] = v.w;
    }
    __syncthreads();

    const int tx = tid & 15;
    const int ty = tid >> 4;
    const int c0 = tx * 8;
    const float* xb = &Xs[(ty * 8) * 129];

    unsigned long long acc[8][4];
    #pragma unroll
    for (int r = 0; r < 8; r++)
        #pragma unroll
        for (int j = 0; j < 4; j++) acc[r][j] = 0ull;

    #pragma unroll 4
    for (int k = 0; k < 128; k++) {
        const ulonglong2* wrow = (const ulonglong2*)&Wt[k * 128 + c0];
        ulonglong2 wa = wrow[0], wb = wrow[1];
        #pragma unroll
        for (int r = 0; r < 8; r++) {
            float xv = xb[r * 129 + k];
            unsigned long long xx;
            asm("mov.b64 %0, {%1, %1};" : "=l"(xx) : "f"(xv));
            asm("fma.rn.f32x2 %0, %1, %2, %0;" : "+l"(acc[r][0]) : "l"(xx), "l"(wa.x));
            asm("fma.rn.f32x2 %0, %1, %2, %0;" : "+l"(acc[r][1]) : "l"(xx), "l"(wa.y));
            asm("fma.rn.f32x2 %0, %1, %2, %0;" : "+l"(acc[r][2]) : "l"(xx), "l"(wb.x));
            asm("fma.rn.f32x2 %0, %1, %2, %0;" : "+l"(acc[r][3]) : "l"(xx), "l"(wb.y));
        }
    }

    #pragma unroll
    for (int r = 0; r < 8; r++) {
        int gr = row0 + ty * 8 + r;
        if (gr >= nrows) break;
        float v[8];
        #pragma unroll
        for (int j = 0; j < 4; j++) {
            float lo, hi;
            asm("mov.b64 {%0, %1}, %2;" : "=f"(lo), "=f"(hi) : "l"(acc[r][j]));
            v[2 * j] = lo; v[2 * j + 1] = hi;
        }
        float4* xwp = (float4*)&XW[(size_t)gr * HD + c0];
        xwp[0] = make_float4(v[0], v[1], v[2], v[3]);
        xwp[1] = make_float4(v[4], v[5], v[6], v[7]);
    }
}

// ---------------- aggregation: out[d] = b + dis[d]^2*xw[d] + sum norm*xw[s] -
// One warp per destination node; lane handles one float4 (4 columns).
__global__ void __launch_bounds__(256)
aggregate_kernel(const float* __restrict__ bias,
                 const float* __restrict__ xw,
                 float* __restrict__ out, int n)
{
    int node = blockIdx.x * 8 + (threadIdx.x >> 5);
    int lane = threadIdx.x & 31;
    if (node >= n) return;

    int beg = g_rowptr[node];
    int end = g_rowptr[node + 1];

    float ds = g_dis[node];
    float sc = ds * ds;
    float4 vs = ((const float4*)(xw + (size_t)node * HD))[lane];
    float4 b4 = ((const float4*)bias)[lane];
    float4 acc;
    acc.x = fmaf(sc, vs.x, b4.x);
    acc.y = fmaf(sc, vs.y, b4.y);
    acc.z = fmaf(sc, vs.z, b4.z);
    acc.w = fmaf(sc, vs.w, b4.w);

    int p = beg;
    for (; p + 4 <= end; p += 4) {
        int2 e0 = g_csr[p + 0];
        int2 e1 = g_csr[p + 1];
        int2 e2 = g_csr[p + 2];
        int2 e3 = g_csr[p + 3];
        float4 v0 = ((const float4*)(xw + (size_t)e0.x * HD))[lane];
        float4 v1 = ((const float4*)(xw + (size_t)e1.x * HD))[lane];
        float4 v2 = ((const float4*)(xw + (size_t)e2.x * HD))[lane];
        float4 v3 = ((const float4*)(xw + (size_t)e3.x * HD))[lane];
        float n0 = __int_as_float(e0.y), n1 = __int_as_float(e1.y);
        float n2 = __int_as_float(e2.y), n3 = __int_as_float(e3.y);
        acc.x = fmaf(n0, v0.x, acc.x); acc.y = fmaf(n0, v0.y, acc.y);
        acc.z = fmaf(n0, v0.z, acc.z); acc.w = fmaf(n0, v0.w, acc.w);
        acc.x = fmaf(n1, v1.x, acc.x); acc.y = fmaf(n1, v1.y, acc.y);
        acc.z = fmaf(n1, v1.z, acc.z); acc.w = fmaf(n1, v1.w, acc.w);
        acc.x = fmaf(n2, v2.x, acc.x); acc.y = fmaf(n2, v2.y, acc.y);
        acc.z = fmaf(n2, v2.z, acc.z); acc.w = fmaf(n2, v2.w, acc.w);
        acc.x = fmaf(n3, v3.x, acc.x); acc.y = fmaf(n3, v3.y, acc.y);
        acc.z = fmaf(n3, v3.z, acc.z); acc.w = fmaf(n3, v3.w, acc.w);
    }
    for (; p < end; p++) {
        int2 e = g_csr[p];
        float4 v = ((const float4*)(xw + (size_t)e.x * HD))[lane];
        float nm = __int_as_float(e.y);
        acc.x = fmaf(nm, v.x, acc.x); acc.y = fmaf(nm, v.y, acc.y);
        acc.z = fmaf(nm, v.z, acc.z); acc.w = fmaf(nm, v.w, acc.w);
    }

    ((float4*)(out + (size_t)node * HD))[lane] = acc;
}

// ---------------- launch ----------------------------------------------------
extern "C" void kernel_launch(void* const* d_in, const int* in_sizes, int n_in,
                              void* d_out, int out_size) {
    const float* emb = (const float*)d_in[0];
    const int*   ew  = (const int*)d_in[1];   // width detected on device
    const float* W1  = (const float*)d_in[2];
    const float* b1  = (const float*)d_in[3];
    const float* W2  = (const float*)d_in[4];
    const float* b2  = (const float*)d_in[5];
    float* out = (float*)d_out;

    const int nrows = in_sizes[0] / HD;       // 50000
    const int E     = in_sizes[1] / 2;        // 600000

    float *xw_p, *h1_p;
    cudaGetSymbolAddress((void**)&xw_p, g_xw);
    cudaGetSymbolAddress((void**)&h1_p, g_h1);

    cudaFuncSetAttribute(gcn_gemm, cudaFuncAttributeMaxDynamicSharedMemorySize,
                         GEMM_SMEM_BYTES);

    const int nb_nodes = (nrows + 255) / 256;   // 196
    const int nb_edges = (E + 255) / 256;       // 2344
    const int nb_gemm  = (nrows + 127) / 128;   // 391
    const int nb_agg   = (nrows + 7) / 8;       // 6250

    // ---- CSR build (shared by both layers) ----
    initdetect_kernel<<<nb_nodes, 256>>>(ew, nrows);
    hist_kernel<<<nb_edges, 256>>>(ew, E);
    scanA_kernel<<<nb_nodes, 256>>>(nrows);
    scanB_kernel<<<1, 256>>>(nb_nodes);
    scanC_kernel<<<nb_nodes, 256>>>(nrows, E);
    fill_kernel<<<nb_edges, 256>>>(ew, E);

    // ---- Layer 1 ----
    gcn_gemm<<<nb_gemm, 256, GEMM_SMEM_BYTES>>>(emb, W1, xw_p, nrows);
    aggregate_kernel<<<nb_agg, 256>>>(b1, xw_p, h1_p, nrows);

    // ---- Layer 2 ----
    gcn_gemm<<<nb_gemm, 256, GEMM_SMEM_BYTES>>>(h1_p, W2, xw_p, nrows);
    aggregate_kernel<<<nb_agg, 256>>>(b2, xw_p, out, nrows);
}